// round 1
// baseline (speedup 1.0000x reference)
#include <cuda_runtime.h>
#include <cstdint>

#define Bv 256
#define Tv 512
#define Iv 128
#define Hv 256
#define G4v 1024
#define REC_CTAS 128
#define MBv 32   // batch rows per CTA (8 tiles)
#define HSv 16   // hidden slice per CTA (16 slices)

// ---------------- scratch (device globals; no cudaMalloc allowed) ----------
__device__ float g_xg[(long long)Tv * Bv * G4v];    // 512 MB gate preacts [t][b][4H]
__device__ float g_hseq[(long long)Tv * Bv * Hv];   // 128 MB layer0 output [t][b][H]
__device__ float g_h[Bv * Hv];                      // current hidden state
__device__ unsigned g_count;
__device__ volatile unsigned g_phase;

// ---------------- helpers ---------------------------------------------------
__device__ __forceinline__ unsigned f2tf(float f) {
    unsigned u;
    asm("cvt.rna.tf32.f32 %0, %1;" : "=r"(u) : "f"(f));
    return u;
}
__device__ __forceinline__ void mma_tf32(float c[4], unsigned a0, unsigned a1,
                                         unsigned a2, unsigned a3,
                                         unsigned b0, unsigned b1) {
    asm volatile(
        "mma.sync.aligned.m16n8k8.row.col.f32.tf32.tf32.f32 "
        "{%0,%1,%2,%3}, {%4,%5,%6,%7}, {%8,%9}, {%0,%1,%2,%3};"
        : "+f"(c[0]), "+f"(c[1]), "+f"(c[2]), "+f"(c[3])
        : "r"(a0), "r"(a1), "r"(a2), "r"(a3), "r"(b0), "r"(b1));
}
__device__ __forceinline__ float sigm(float x) { return 1.0f / (1.0f + expf(-x)); }

// ---------------- input-projection GEMM (tf32 mma) -------------------------
// out[m][n] = sum_k A[m][k] * W[n][k] + bias1[n] + bias2[n]
// m = t*B + b; A row address = base + (m%B)*sB + (m/B)*sT  (m/B with B=256)
// CTA tile: 128(M) x 64(N), K chunked by 32. 256 threads = 8 warps (4M x 2N).
__global__ void __launch_bounds__(256) gemm_tf32(
    const float* __restrict__ A_ext, int useHseq, long long sB, long long sT, int K,
    const float* __restrict__ W, const float* __restrict__ bias1,
    const float* __restrict__ bias2)
{
    __shared__ float As[128][36];
    __shared__ float Bs[64][36];

    if (blockIdx.x == 0 && blockIdx.y == 0 && threadIdx.x == 0) {
        g_count = 0;
        g_phase = 0;  // reset grid barrier for the next recurrence kernel
    }

    const float* A = useHseq ? (const float*)g_hseq : A_ext;

    int tid  = threadIdx.x;
    int lane = tid & 31, wid = tid >> 5;
    int wm = wid & 3, wn = wid >> 2;
    int mbase = wm * 32, nbase = wn * 32;
    int grp = lane >> 2, tig = lane & 3;
    int ctaN = blockIdx.x, ctaM = blockIdx.y;

    float acc[2][4][4];
#pragma unroll
    for (int a = 0; a < 2; a++)
#pragma unroll
        for (int b = 0; b < 4; b++)
#pragma unroll
            for (int c = 0; c < 4; c++) acc[a][b][c] = 0.0f;

    for (int k0 = 0; k0 < K; k0 += 32) {
        // stage A tile: 128 rows x 32 cols = 1024 float4
#pragma unroll
        for (int i = 0; i < 4; i++) {
            int id = tid + i * 256;
            int r = id >> 3, c4 = id & 7;
            long long grow = (long long)ctaM * 128 + r;
            const float* src = A + (grow & (Bv - 1)) * sB + (grow >> 8) * sT + k0 + c4 * 4;
            float4 v = *(const float4*)src;
            As[r][c4 * 4 + 0] = __uint_as_float(f2tf(v.x));
            As[r][c4 * 4 + 1] = __uint_as_float(f2tf(v.y));
            As[r][c4 * 4 + 2] = __uint_as_float(f2tf(v.z));
            As[r][c4 * 4 + 3] = __uint_as_float(f2tf(v.w));
        }
        // stage B tile: 64 rows x 32 cols = 512 float4
#pragma unroll
        for (int i = 0; i < 2; i++) {
            int id = tid + i * 256;
            int r = id >> 3, c4 = id & 7;
            const float* src = W + (long long)(ctaN * 64 + r) * K + k0 + c4 * 4;
            float4 v = *(const float4*)src;
            Bs[r][c4 * 4 + 0] = __uint_as_float(f2tf(v.x));
            Bs[r][c4 * 4 + 1] = __uint_as_float(f2tf(v.y));
            Bs[r][c4 * 4 + 2] = __uint_as_float(f2tf(v.z));
            Bs[r][c4 * 4 + 3] = __uint_as_float(f2tf(v.w));
        }
        __syncthreads();

#pragma unroll
        for (int kk = 0; kk < 32; kk += 8) {
            unsigned a[2][4];
#pragma unroll
            for (int mt = 0; mt < 2; mt++) {
                int row = mbase + mt * 16 + grp;
                a[mt][0] = __float_as_uint(As[row][kk + tig]);
                a[mt][1] = __float_as_uint(As[row + 8][kk + tig]);
                a[mt][2] = __float_as_uint(As[row][kk + tig + 4]);
                a[mt][3] = __float_as_uint(As[row + 8][kk + tig + 4]);
            }
#pragma unroll
            for (int nt = 0; nt < 4; nt++) {
                int nr = nbase + nt * 8 + grp;
                unsigned b0 = __float_as_uint(Bs[nr][kk + tig]);
                unsigned b1 = __float_as_uint(Bs[nr][kk + tig + 4]);
#pragma unroll
                for (int mt = 0; mt < 2; mt++)
                    mma_tf32(acc[mt][nt], a[mt][0], a[mt][1], a[mt][2], a[mt][3], b0, b1);
            }
        }
        __syncthreads();
    }

    // epilogue -> g_xg[m*1024 + n]
#pragma unroll
    for (int mt = 0; mt < 2; mt++) {
#pragma unroll
        for (int nt = 0; nt < 4; nt++) {
            long long grow = (long long)ctaM * 128 + mbase + mt * 16 + grp;
            int gcol = ctaN * 64 + nbase + nt * 8 + 2 * tig;
            float bb0 = bias1[gcol] + bias2[gcol];
            float bb1 = bias1[gcol + 1] + bias2[gcol + 1];
            g_xg[grow * G4v + gcol]           = acc[mt][nt][0] + bb0;
            g_xg[grow * G4v + gcol + 1]       = acc[mt][nt][1] + bb1;
            g_xg[(grow + 8) * G4v + gcol]     = acc[mt][nt][2] + bb0;
            g_xg[(grow + 8) * G4v + gcol + 1] = acc[mt][nt][3] + bb1;
        }
    }
}

// ---------------- persistent recurrence kernel ------------------------------
// 128 CTAs: blockIdx = bt (8 batch tiles of 32) x hs (16 H-slices of 16).
// W_hh slice (64 gate rows x 256) tf32 in SMEM; c state in SMEM; own h slice
// in registers; full h exchanged through g_h (L2) + software grid barrier.
__global__ void __launch_bounds__(256, 1) lstm_rec(
    const int* __restrict__ lengths, const float* __restrict__ W_hh, int writeSeq)
{
    extern __shared__ float sm[];
    float (*Ws)[260]    = (float(*)[260])sm;                           // 64x260
    float (*Hsm)[260]   = (float(*)[260])(sm + 64 * 260);              // 32x260
    float (*gates)[68]  = (float(*)[68])(sm + 64 * 260 + 32 * 260);    // 32x68
    float (*cst)[16]    = (float(*)[16])(sm + 64 * 260 + 32 * 260 + 32 * 68);
    int*   slen         = (int*)(sm + 64 * 260 + 32 * 260 + 32 * 68 + 32 * 16);
    int*   pmax         = slen + 32;

    int tid = threadIdx.x, lane = tid & 31, wid = tid >> 5;
    int bt = blockIdx.x & 7;
    int hs = blockIdx.x >> 3;
    int wm = wid & 1, wn = wid >> 1;   // 2(M) x 4(N) warps, warp tile 16x16
    int grp = lane >> 2, tig = lane & 3;

    // init W slice (tf32-rounded), c state, lengths
#pragma unroll
    for (int i = 0; i < 16; i++) {
        int id = tid + i * 256;
        int r = id >> 6, c4 = id & 63;
        long long grow = (long long)(r >> 4) * Hv + hs * HSv + (r & 15);
        float4 v = *(const float4*)(W_hh + grow * Hv + c4 * 4);
        Ws[r][c4 * 4 + 0] = __uint_as_float(f2tf(v.x));
        Ws[r][c4 * 4 + 1] = __uint_as_float(f2tf(v.y));
        Ws[r][c4 * 4 + 2] = __uint_as_float(f2tf(v.z));
        Ws[r][c4 * 4 + 3] = __uint_as_float(f2tf(v.w));
    }
    if (tid < 32) slen[tid] = lengths[bt * MBv + tid];
    for (int p = tid; p < MBv * HSv; p += 256) ((float*)cst)[p] = 0.0f;
    __syncthreads();
    if (tid == 0) {
        int m = 0;
        for (int i = 0; i < 32; i++) m = max(m, slen[i]);
        pmax[0] = m;
    }
    __syncthreads();
    int maxlen = pmax[0];

    float hmy[2] = {0.0f, 0.0f};  // this thread's 2 (b,j) hidden values
    unsigned lp = 0;

    for (int t = 0; t < Tv; t++) {
        bool active = (t < maxlen);
        if (active) {
            // stage xg tile -> gates  (32 rows x 64 cols)
#pragma unroll
            for (int i = 0; i < 2; i++) {
                int id = tid + i * 256;
                int b = id >> 4, rem = id & 15;
                int g = rem >> 2, c4 = rem & 3;
                float4 v = *(const float4*)(g_xg +
                    ((long long)t * Bv + bt * MBv + b) * G4v + g * Hv + hs * HSv + c4 * 4);
                *(float4*)&gates[b][g * 16 + c4 * 4] = v;
            }
            if (t > 0) {
                // stage full h tile (32 x 256)
#pragma unroll
                for (int i = 0; i < 8; i++) {
                    int id = tid + i * 256;
                    int b = id >> 6, c4 = id & 63;
                    float4 v = *(const float4*)(g_h + (long long)(bt * MBv + b) * Hv + c4 * 4);
                    *(float4*)&Hsm[b][c4 * 4] = v;
                }
            }
            __syncthreads();

            float acc[2][4] = {{0, 0, 0, 0}, {0, 0, 0, 0}};
            if (t > 0) {
#pragma unroll
                for (int kk = 0; kk < Hv; kk += 8) {
                    int arow = wm * 16 + grp;
                    unsigned a0 = f2tf(Hsm[arow][kk + tig]);
                    unsigned a1 = f2tf(Hsm[arow + 8][kk + tig]);
                    unsigned a2 = f2tf(Hsm[arow][kk + tig + 4]);
                    unsigned a3 = f2tf(Hsm[arow + 8][kk + tig + 4]);
#pragma unroll
                    for (int nt = 0; nt < 2; nt++) {
                        int nr = wn * 16 + nt * 8 + grp;
                        unsigned b0 = __float_as_uint(Ws[nr][kk + tig]);
                        unsigned b1 = __float_as_uint(Ws[nr][kk + tig + 4]);
                        mma_tf32(acc[nt], a0, a1, a2, a3, b0, b1);
                    }
                }
            }
            // accumulate mma result into gates
#pragma unroll
            for (int nt = 0; nt < 2; nt++) {
                int row = wm * 16 + grp;
                int col = wn * 16 + nt * 8 + 2 * tig;
                gates[row][col]         += acc[nt][0];
                gates[row][col + 1]     += acc[nt][1];
                gates[row + 8][col]     += acc[nt][2];
                gates[row + 8][col + 1] += acc[nt][3];
            }
            __syncthreads();

            // activations + state update (each thread: 2 (b,j) pairs)
#pragma unroll
            for (int i = 0; i < 2; i++) {
                int p = tid + i * 256;
                int b = p >> 4, j = p & 15;
                if (t < slen[b]) {
                    float gi = gates[b][j];
                    float gf = gates[b][16 + j];
                    float gg = gates[b][32 + j];
                    float go = gates[b][48 + j];
                    float iv = sigm(gi), fv = sigm(gf);
                    float gv = tanhf(gg), ov = sigm(go);
                    float cn = fv * cst[b][j] + iv * gv;
                    cst[b][j] = cn;
                    hmy[i] = ov * tanhf(cn);
                }
                g_h[(long long)(bt * MBv + b) * Hv + hs * HSv + j] = hmy[i];
                if (writeSeq)
                    g_hseq[((long long)t * Bv + bt * MBv + b) * Hv + hs * HSv + j] = hmy[i];
            }
        } else if (writeSeq) {
            // tile fully frozen: only keep layer-1 input stream consistent
#pragma unroll
            for (int i = 0; i < 2; i++) {
                int p = tid + i * 256;
                int b = p >> 4, j = p & 15;
                g_hseq[((long long)t * Bv + bt * MBv + b) * Hv + hs * HSv + j] = hmy[i];
            }
        }

        // grid barrier
        __threadfence();
        __syncthreads();
        lp++;
        if (tid == 0) {
            unsigned old = atomicAdd(&g_count, 1u);
            if (old == REC_CTAS - 1) {
                g_count = 0;
                __threadfence();
                g_phase = lp;
            } else {
                while (g_phase < lp) {}
            }
        }
        __syncthreads();
        __threadfence();
    }
}

// ---------------- final FC + softmax ----------------------------------------
__global__ void fc_softmax(const float* __restrict__ W_fc,
                           const float* __restrict__ b_fc, float* __restrict__ out)
{
    int b = blockIdx.x, lane = threadIdx.x;
    float logit[10];
#pragma unroll
    for (int c = 0; c < 10; c++) {
        float s = 0.0f;
        for (int h = lane; h < Hv; h += 32)
            s += g_h[b * Hv + h] * W_fc[c * Hv + h];
#pragma unroll
        for (int o = 16; o; o >>= 1) s += __shfl_down_sync(0xffffffffu, s, o);
        logit[c] = s;
    }
    if (lane == 0) {
        float mx = -1e30f;
#pragma unroll
        for (int c = 0; c < 10; c++) {
            logit[c] += b_fc[c];
            mx = fmaxf(mx, logit[c]);
        }
        float sum = 0.0f;
#pragma unroll
        for (int c = 0; c < 10; c++) {
            logit[c] = expf(logit[c] - mx);
            sum += logit[c];
        }
        float inv = 1.0f / sum;
#pragma unroll
        for (int c = 0; c < 10; c++) out[b * 10 + c] = logit[c] * inv;
    }
}

// ---------------- host launcher ---------------------------------------------
extern "C" void kernel_launch(void* const* d_in, const int* in_sizes, int n_in,
                              void* d_out, int out_size)
{
    const float* x      = (const float*)d_in[0];
    const int*   length = (const int*)d_in[1];
    const float* W_fc   = (const float*)d_in[2];
    const float* b_fc   = (const float*)d_in[3];
    const float* W_ih0  = (const float*)d_in[4];
    const float* W_hh0  = (const float*)d_in[5];
    const float* b_ih0  = (const float*)d_in[6];
    const float* b_hh0  = (const float*)d_in[7];
    const float* W_ih1  = (const float*)d_in[8];
    const float* W_hh1  = (const float*)d_in[9];
    const float* b_ih1  = (const float*)d_in[10];
    const float* b_hh1  = (const float*)d_in[11];
    float* out = (float*)d_out;

    int smem = (64 * 260 + 32 * 260 + 32 * 68 + 32 * 16 + 34) * 4;
    cudaFuncSetAttribute(lstm_rec, cudaFuncAttributeMaxDynamicSharedMemorySize, smem);

    dim3 ggrid(G4v / 64, (Tv * Bv) / 128);

    // layer 0 input projection: Xg = X @ W_ih0^T + (b_ih0 + b_hh0)
    gemm_tf32<<<ggrid, 256>>>(x, 0, (long long)Tv * Iv, (long long)Iv, Iv,
                              W_ih0, b_ih0, b_hh0);
    // layer 0 recurrence (writes g_hseq)
    lstm_rec<<<REC_CTAS, 256, smem>>>(length, W_hh0, 1);
    // layer 1 input projection: Xg = hseq @ W_ih1^T + (b_ih1 + b_hh1)
    gemm_tf32<<<ggrid, 256>>>(nullptr, 1, (long long)Hv, (long long)Bv * Hv, Hv,
                              W_ih1, b_ih1, b_hh1);
    // layer 1 recurrence (final h stays in g_h)
    lstm_rec<<<REC_CTAS, 256, smem>>>(length, W_hh1, 0);
    // FC + softmax
    fc_softmax<<<Bv, 32>>>(W_fc, b_fc, out);
}

// round 2
// speedup vs baseline: 1.2309x; 1.2309x over previous
#include <cuda_runtime.h>
#include <cstdint>

#define Bv 256
#define Tv 512
#define Iv 128
#define Hv 256
#define G4v 1024
#define REC_CTAS 128
#define MBv 32   // batch rows per CTA (8 groups)
#define HSv 16   // hidden slice per CTA (16 slices per group)

// ---------------- scratch (device globals; no cudaMalloc allowed) ----------
__device__ float g_xg[(long long)Tv * Bv * G4v];    // 512 MB gate preacts [t][b][4H]
__device__ float g_hseq[(long long)Tv * Bv * Hv];   // 128 MB layer0 output [t][b][H]
__device__ float g_hbuf[2][Bv * Hv];                // double-buffered hidden state
__device__ float g_hfinal[Bv * Hv];                 // final hidden state for FC
__device__ unsigned g_flags[8 * 32];                // per-group flag line (32 ints = 128B)

// ---------------- helpers ---------------------------------------------------
__device__ __forceinline__ unsigned f2tf(float f) {
    unsigned u;
    asm("cvt.rna.tf32.f32 %0, %1;" : "=r"(u) : "f"(f));
    return u;
}
__device__ __forceinline__ void mma_tf32(float c[4], unsigned a0, unsigned a1,
                                         unsigned a2, unsigned a3,
                                         unsigned b0, unsigned b1) {
    asm volatile(
        "mma.sync.aligned.m16n8k8.row.col.f32.tf32.tf32.f32 "
        "{%0,%1,%2,%3}, {%4,%5,%6,%7}, {%8,%9}, {%0,%1,%2,%3};"
        : "+f"(c[0]), "+f"(c[1]), "+f"(c[2]), "+f"(c[3])
        : "r"(a0), "r"(a1), "r"(a2), "r"(a3), "r"(b0), "r"(b1));
}
__device__ __forceinline__ float sigm(float x) { return 1.0f / (1.0f + expf(-x)); }

// ---------------- input-projection GEMM (tf32 mma) -------------------------
// out[m][n] = sum_k A[m][k] * W[n][k] + bias1[n] + bias2[n]
// m = t*B + b; A row address = base + (m%B)*sB + (m/B)*sT  (m/B with B=256)
// CTA tile: 128(M) x 64(N), K chunked by 32. 256 threads = 8 warps (4M x 2N).
__global__ void __launch_bounds__(256) gemm_tf32(
    const float* __restrict__ A_ext, int useHseq, long long sB, long long sT, int K,
    const float* __restrict__ W, const float* __restrict__ bias1,
    const float* __restrict__ bias2)
{
    __shared__ float As[128][36];
    __shared__ float Bs[64][36];

    // reset recurrence flags for the lstm_rec kernel that follows this GEMM
    if (blockIdx.x == 0 && blockIdx.y == 0 && threadIdx.x < 256)
        g_flags[threadIdx.x] = 0u;

    const float* A = useHseq ? (const float*)g_hseq : A_ext;

    int tid  = threadIdx.x;
    int lane = tid & 31, wid = tid >> 5;
    int wm = wid & 3, wn = wid >> 2;
    int mbase = wm * 32, nbase = wn * 32;
    int grp = lane >> 2, tig = lane & 3;
    int ctaN = blockIdx.x, ctaM = blockIdx.y;

    float acc[2][4][4];
#pragma unroll
    for (int a = 0; a < 2; a++)
#pragma unroll
        for (int b = 0; b < 4; b++)
#pragma unroll
            for (int c = 0; c < 4; c++) acc[a][b][c] = 0.0f;

    for (int k0 = 0; k0 < K; k0 += 32) {
#pragma unroll
        for (int i = 0; i < 4; i++) {
            int id = tid + i * 256;
            int r = id >> 3, c4 = id & 7;
            long long grow = (long long)ctaM * 128 + r;
            const float* src = A + (grow & (Bv - 1)) * sB + (grow >> 8) * sT + k0 + c4 * 4;
            float4 v = *(const float4*)src;
            As[r][c4 * 4 + 0] = __uint_as_float(f2tf(v.x));
            As[r][c4 * 4 + 1] = __uint_as_float(f2tf(v.y));
            As[r][c4 * 4 + 2] = __uint_as_float(f2tf(v.z));
            As[r][c4 * 4 + 3] = __uint_as_float(f2tf(v.w));
        }
#pragma unroll
        for (int i = 0; i < 2; i++) {
            int id = tid + i * 256;
            int r = id >> 3, c4 = id & 7;
            const float* src = W + (long long)(ctaN * 64 + r) * K + k0 + c4 * 4;
            float4 v = *(const float4*)src;
            Bs[r][c4 * 4 + 0] = __uint_as_float(f2tf(v.x));
            Bs[r][c4 * 4 + 1] = __uint_as_float(f2tf(v.y));
            Bs[r][c4 * 4 + 2] = __uint_as_float(f2tf(v.z));
            Bs[r][c4 * 4 + 3] = __uint_as_float(f2tf(v.w));
        }
        __syncthreads();

#pragma unroll
        for (int kk = 0; kk < 32; kk += 8) {
            unsigned a[2][4];
#pragma unroll
            for (int mt = 0; mt < 2; mt++) {
                int row = mbase + mt * 16 + grp;
                a[mt][0] = __float_as_uint(As[row][kk + tig]);
                a[mt][1] = __float_as_uint(As[row + 8][kk + tig]);
                a[mt][2] = __float_as_uint(As[row][kk + tig + 4]);
                a[mt][3] = __float_as_uint(As[row + 8][kk + tig + 4]);
            }
#pragma unroll
            for (int nt = 0; nt < 4; nt++) {
                int nr = nbase + nt * 8 + grp;
                unsigned b0 = __float_as_uint(Bs[nr][kk + tig]);
                unsigned b1 = __float_as_uint(Bs[nr][kk + tig + 4]);
#pragma unroll
                for (int mt = 0; mt < 2; mt++)
                    mma_tf32(acc[mt][nt], a[mt][0], a[mt][1], a[mt][2], a[mt][3], b0, b1);
            }
        }
        __syncthreads();
    }

#pragma unroll
    for (int mt = 0; mt < 2; mt++) {
#pragma unroll
        for (int nt = 0; nt < 4; nt++) {
            long long grow = (long long)ctaM * 128 + mbase + mt * 16 + grp;
            int gcol = ctaN * 64 + nbase + nt * 8 + 2 * tig;
            float bb0 = bias1[gcol] + bias2[gcol];
            float bb1 = bias1[gcol + 1] + bias2[gcol + 1];
            g_xg[grow * G4v + gcol]           = acc[mt][nt][0] + bb0;
            g_xg[grow * G4v + gcol + 1]       = acc[mt][nt][1] + bb1;
            g_xg[(grow + 8) * G4v + gcol]     = acc[mt][nt][2] + bb0;
            g_xg[(grow + 8) * G4v + gcol + 1] = acc[mt][nt][3] + bb1;
        }
    }
}

// ---------------- persistent recurrence kernel ------------------------------
// 128 CTAs: blockIdx = bt (8 batch groups of 32 rows) x hs (16 H-slices of 16).
// Groups are independent: only the 16 CTAs sharing bt exchange h.
// Sync: per-group release/acquire flags (no atomics), double-buffered g_hbuf.
__global__ void __launch_bounds__(256, 1) lstm_rec(
    const int* __restrict__ lengths, const float* __restrict__ W_hh, int writeSeq)
{
    extern __shared__ float sm[];
    float (*Ws)[260]    = (float(*)[260])sm;                           // 64x260
    float (*Hsm)[260]   = (float(*)[260])(sm + 64 * 260);              // 32x260
    float (*gates)[68]  = (float(*)[68])(sm + 64 * 260 + 32 * 260);    // 32x68
    float (*cst)[16]    = (float(*)[16])(sm + 64 * 260 + 32 * 260 + 32 * 68);
    int*   slen         = (int*)(sm + 64 * 260 + 32 * 260 + 32 * 68 + 32 * 16);
    int*   pmax         = slen + 32;

    int tid = threadIdx.x, lane = tid & 31, wid = tid >> 5;
    int bt = blockIdx.x & 7;
    int hs = blockIdx.x >> 3;
    int wm = wid & 1, wn = wid >> 1;   // 2(M) x 4(N) warps, warp tile 16x16
    int grp = lane >> 2, tig = lane & 3;

    // init W slice (tf32-rounded), c state, lengths
#pragma unroll
    for (int i = 0; i < 16; i++) {
        int id = tid + i * 256;
        int r = id >> 6, c4 = id & 63;
        long long grow = (long long)(r >> 4) * Hv + hs * HSv + (r & 15);
        float4 v = *(const float4*)(W_hh + grow * Hv + c4 * 4);
        Ws[r][c4 * 4 + 0] = __uint_as_float(f2tf(v.x));
        Ws[r][c4 * 4 + 1] = __uint_as_float(f2tf(v.y));
        Ws[r][c4 * 4 + 2] = __uint_as_float(f2tf(v.z));
        Ws[r][c4 * 4 + 3] = __uint_as_float(f2tf(v.w));
    }
    if (tid < 32) slen[tid] = lengths[bt * MBv + tid];
    for (int p = tid; p < MBv * HSv; p += 256) ((float*)cst)[p] = 0.0f;
    __syncthreads();
    if (tid == 0) {
        int m = 0;
        for (int i = 0; i < 32; i++) m = max(m, slen[i]);
        pmax[0] = m;
    }
    __syncthreads();
    int maxlen = pmax[0];

    unsigned* myflag = g_flags + bt * 32 + hs;
    const unsigned* grpflags = g_flags + bt * 32;

    float hmy[2] = {0.0f, 0.0f};  // this thread's 2 (b,j) hidden values
    float4 xgr[2];

    // prefetch xg for t=0
#pragma unroll
    for (int i = 0; i < 2; i++) {
        int id = tid + i * 256;
        int b = id >> 4, rem = id & 15;
        int g = rem >> 2, c4 = rem & 3;
        xgr[i] = *(const float4*)(g_xg +
            ((long long)(bt * MBv + b)) * G4v + g * Hv + hs * HSv + c4 * 4);
    }

    for (int t = 0; t < maxlen; t++) {
        // wait: all 16 group CTAs finished step t-1 (h(t-1) visible,
        // readers of buffer t&1 from step t-1 are done -> safe to overwrite)
        if (t > 0) {
            if (tid < 16) {
                unsigned v;
                const unsigned* fp = grpflags + tid;
                do {
                    asm volatile("ld.acquire.gpu.u32 %0, [%1];" : "=r"(v) : "l"(fp));
                } while (v < (unsigned)t);
            }
        }
        __syncthreads();

        // stage prefetched xg tile -> gates (32 rows x 64 cols)
#pragma unroll
        for (int i = 0; i < 2; i++) {
            int id = tid + i * 256;
            int b = id >> 4, rem = id & 15;
            int g = rem >> 2, c4 = rem & 3;
            *(float4*)&gates[b][g * 16 + c4 * 4] = xgr[i];
        }
        // stage full h(t-1) tile (32 x 256), pre-converted to tf32
        if (t > 0) {
            const float* hb = g_hbuf[(t - 1) & 1];
#pragma unroll
            for (int i = 0; i < 8; i++) {
                int id = tid + i * 256;
                int b = id >> 6, c4 = id & 63;
                float4 v = *(const float4*)(hb + (long long)(bt * MBv + b) * Hv + c4 * 4);
                Hsm[b][c4 * 4 + 0] = __uint_as_float(f2tf(v.x));
                Hsm[b][c4 * 4 + 1] = __uint_as_float(f2tf(v.y));
                Hsm[b][c4 * 4 + 2] = __uint_as_float(f2tf(v.z));
                Hsm[b][c4 * 4 + 3] = __uint_as_float(f2tf(v.w));
            }
        }
        __syncthreads();

        // prefetch next step's xg (independent of h; overlaps with mma)
        if (t + 1 < maxlen) {
#pragma unroll
            for (int i = 0; i < 2; i++) {
                int id = tid + i * 256;
                int b = id >> 4, rem = id & 15;
                int g = rem >> 2, c4 = rem & 3;
                xgr[i] = *(const float4*)(g_xg +
                    ((long long)(t + 1) * Bv + bt * MBv + b) * G4v + g * Hv + hs * HSv + c4 * 4);
            }
        }

        float acc[2][4] = {{0, 0, 0, 0}, {0, 0, 0, 0}};
        if (t > 0) {
#pragma unroll
            for (int kk = 0; kk < Hv; kk += 8) {
                int arow = wm * 16 + grp;
                unsigned a0 = __float_as_uint(Hsm[arow][kk + tig]);
                unsigned a1 = __float_as_uint(Hsm[arow + 8][kk + tig]);
                unsigned a2 = __float_as_uint(Hsm[arow][kk + tig + 4]);
                unsigned a3 = __float_as_uint(Hsm[arow + 8][kk + tig + 4]);
#pragma unroll
                for (int nt = 0; nt < 2; nt++) {
                    int nr = wn * 16 + nt * 8 + grp;
                    unsigned b0 = __float_as_uint(Ws[nr][kk + tig]);
                    unsigned b1 = __float_as_uint(Ws[nr][kk + tig + 4]);
                    mma_tf32(acc[nt], a0, a1, a2, a3, b0, b1);
                }
            }
        }
        // accumulate mma result into gates
#pragma unroll
        for (int nt = 0; nt < 2; nt++) {
            int row = wm * 16 + grp;
            int col = wn * 16 + nt * 8 + 2 * tig;
            gates[row][col]         += acc[nt][0];
            gates[row][col + 1]     += acc[nt][1];
            gates[row + 8][col]     += acc[nt][2];
            gates[row + 8][col + 1] += acc[nt][3];
        }
        __syncthreads();

        // activations + state update (each thread: 2 (b,j) pairs)
        float* hw = g_hbuf[t & 1];
#pragma unroll
        for (int i = 0; i < 2; i++) {
            int p = tid + i * 256;
            int b = p >> 4, j = p & 15;
            bool act = (t < slen[b]);
            if (act) {
                float gi = gates[b][j];
                float gf = gates[b][16 + j];
                float gg = gates[b][32 + j];
                float go = gates[b][48 + j];
                float iv = sigm(gi), fv = sigm(gf);
                float gv = tanhf(gg), ov = sigm(go);
                float cn = fv * cst[b][j] + iv * gv;
                cst[b][j] = cn;
                hmy[i] = ov * tanhf(cn);
            }
            hw[(long long)(bt * MBv + b) * Hv + hs * HSv + j] = hmy[i];
            if (writeSeq && act)
                g_hseq[((long long)t * Bv + bt * MBv + b) * Hv + hs * HSv + j] = hmy[i];
        }

        __syncthreads();
        if (tid == 0) {
            unsigned nv = (unsigned)(t + 1);
            asm volatile("st.release.gpu.u32 [%0], %1;" :: "l"(myflag), "r"(nv) : "memory");
        }
    }

    // publish final hidden state for FC
#pragma unroll
    for (int i = 0; i < 2; i++) {
        int p = tid + i * 256;
        int b = p >> 4, j = p & 15;
        g_hfinal[(long long)(bt * MBv + b) * Hv + hs * HSv + j] = hmy[i];
    }
}

// ---------------- final FC + softmax ----------------------------------------
__global__ void fc_softmax(const float* __restrict__ W_fc,
                           const float* __restrict__ b_fc, float* __restrict__ out)
{
    int b = blockIdx.x, lane = threadIdx.x;
    float logit[10];
#pragma unroll
    for (int c = 0; c < 10; c++) {
        float s = 0.0f;
        for (int h = lane; h < Hv; h += 32)
            s += g_hfinal[b * Hv + h] * W_fc[c * Hv + h];
#pragma unroll
        for (int o = 16; o; o >>= 1) s += __shfl_down_sync(0xffffffffu, s, o);
        logit[c] = s;
    }
    if (lane == 0) {
        float mx = -1e30f;
#pragma unroll
        for (int c = 0; c < 10; c++) {
            logit[c] += b_fc[c];
            mx = fmaxf(mx, logit[c]);
        }
        float sum = 0.0f;
#pragma unroll
        for (int c = 0; c < 10; c++) {
            logit[c] = expf(logit[c] - mx);
            sum += logit[c];
        }
        float inv = 1.0f / sum;
#pragma unroll
        for (int c = 0; c < 10; c++) out[b * 10 + c] = logit[c] * inv;
    }
}

// ---------------- host launcher ---------------------------------------------
extern "C" void kernel_launch(void* const* d_in, const int* in_sizes, int n_in,
                              void* d_out, int out_size)
{
    const float* x      = (const float*)d_in[0];
    const int*   length = (const int*)d_in[1];
    const float* W_fc   = (const float*)d_in[2];
    const float* b_fc   = (const float*)d_in[3];
    const float* W_ih0  = (const float*)d_in[4];
    const float* W_hh0  = (const float*)d_in[5];
    const float* b_ih0  = (const float*)d_in[6];
    const float* b_hh0  = (const float*)d_in[7];
    const float* W_ih1  = (const float*)d_in[8];
    const float* W_hh1  = (const float*)d_in[9];
    const float* b_ih1  = (const float*)d_in[10];
    const float* b_hh1  = (const float*)d_in[11];
    float* out = (float*)d_out;

    int smem = (64 * 260 + 32 * 260 + 32 * 68 + 32 * 16 + 34) * 4;
    cudaFuncSetAttribute(lstm_rec, cudaFuncAttributeMaxDynamicSharedMemorySize, smem);

    dim3 ggrid(G4v / 64, (Tv * Bv) / 128);

    // layer 0 input projection: Xg = X @ W_ih0^T + (b_ih0 + b_hh0)
    gemm_tf32<<<ggrid, 256>>>(x, 0, (long long)Tv * Iv, (long long)Iv, Iv,
                              W_ih0, b_ih0, b_hh0);
    // layer 0 recurrence (writes g_hseq)
    lstm_rec<<<REC_CTAS, 256, smem>>>(length, W_hh0, 1);
    // layer 1 input projection: Xg = hseq @ W_ih1^T + (b_ih1 + b_hh1)
    gemm_tf32<<<ggrid, 256>>>(nullptr, 1, (long long)Hv, (long long)Bv * Hv, Hv,
                              W_ih1, b_ih1, b_hh1);
    // layer 1 recurrence (final h -> g_hfinal)
    lstm_rec<<<REC_CTAS, 256, smem>>>(length, W_hh1, 0);
    // FC + softmax
    fc_softmax<<<Bv, 32>>>(W_fc, b_fc, out);
}